// round 10
// baseline (speedup 1.0000x reference)
#include <cuda_runtime.h>

#define THREADS 512
#define TW      120   // level-6 outputs per tile
#define NTILES  35    // ceil(4102 / 120)

// db4 reversed decomposition filters as literal immediates (FFMA-imm, rt=1)
#define RL0 ( 0.23037781330885523f)
#define RL1 ( 0.7148465705525415f)
#define RL2 ( 0.6308807679295904f)
#define RL3 (-0.02798376941698385f)
#define RL4 (-0.18703481171888114f)
#define RL5 ( 0.030841381835986965f)
#define RL6 ( 0.032883011666982945f)
#define RL7 (-0.010597401784997278f)
#define RH0 (-0.010597401784997278f)
#define RH1 (-0.032883011666982945f)
#define RH2 ( 0.030841381835986965f)
#define RH3 ( 0.18703481171888114f)
#define RH4 (-0.02798376941698385f)
#define RH5 (-0.6308807679295904f)
#define RH6 ( 0.7148465705525415f)
#define RH7 (-0.23037781330885523f)

// 8-tap A/D dot product on scalar window w[0..7]
#define TAPSW(w, A, D) do {                                             \
    A = (w)[0] * RL0;          D = (w)[0] * RH0;                        \
    A = fmaf((w)[1], RL1, A);  D = fmaf((w)[1], RH1, D);                \
    A = fmaf((w)[2], RL2, A);  D = fmaf((w)[2], RH2, D);                \
    A = fmaf((w)[3], RL3, A);  D = fmaf((w)[3], RH3, D);                \
    A = fmaf((w)[4], RL4, A);  D = fmaf((w)[4], RH4, D);                \
    A = fmaf((w)[5], RL5, A);  D = fmaf((w)[5], RH5, D);                \
    A = fmaf((w)[6], RL6, A);  D = fmaf((w)[6], RH6, D);                \
    A = fmaf((w)[7], RL7, A);  D = fmaf((w)[7], RH7, D);                \
} while (0)

__global__ __launch_bounds__(THREADS)
void dwt6_kernel(const float* __restrict__ x, float* __restrict__ out)
{
    // M[l] = length of cA_l per row (l=0 is the input)
    constexpr int M[7] = {262144, 131075, 65541, 32774, 16390, 8198, 4102};
    // Output element offsets: order cA6, cD6, cD5, cD4, cD3, cD2, cD1
    constexpr long long DOFF[7] = {0, 8390848LL, 4196224LL, 2098688LL,
                                   1049728LL, 525056LL, 262528LL};
    constexpr int N0 = 262144;

    // bufA: cA1/cA3/cA5 (w1<=4026 +ofs10 +8); bufB: cA2/cA4 (w2<=2010)
    __shared__ __align__(16) float bufA[4048];
    __shared__ __align__(16) float bufB[2032];

    const int tile = blockIdx.x;   // 0..34
    const int row  = blockIdx.y;   // 0..63
    const int tid  = threadIdx.x;

    int lo[7], hi[7];
    lo[6] = tile * TW;
    hi[6] = min(lo[6] + TW, M[6]);
#pragma unroll
    for (int l = 5; l >= 1; --l) {
        lo[l] = max(2 * lo[l + 1] - 6, 0);   // always even
        hi[l] = min(2 * hi[l + 1], M[l]);
    }

    const float* xr = x + (size_t)row * N0;

    // ---- Level 1: pairs straight from gmem (3 dense LDG.128 / pair) ----
    {
        const int llo = lo[1], lhi = hi[1];
        const int ofs = 8 + (llo & 3);                  // data offset in bufA
        const int w1  = lhi - llo;
        const int al  = tile * (TW << 5);
        const int bl  = min(al + (TW << 5), M[1]);
        float* dA   = bufA + ofs - llo;
        float* outD = out + DOFF[1] + (size_t)row * M[1];

        if (tid < 16) bufA[tid < 8 ? ofs - 8 + tid : w1 + ofs - 8 + tid] = 0.0f;

        for (int i = llo + 2 * tid; i < lhi; i += 2 * THREADS) {
            const int g = 2 * i - 8;                    // 16B-aligned
            float w[12];
            if (g >= 0 && g + 12 <= N0) {
                const float4* p = reinterpret_cast<const float4*>(xr + g);
                const float4 a = p[0], b = p[1], c = p[2];
                w[0]=a.x; w[1]=a.y; w[2]=a.z;  w[3]=a.w;
                w[4]=b.x; w[5]=b.y; w[6]=b.z;  w[7]=b.w;
                w[8]=c.x; w[9]=c.y; w[10]=c.z; w[11]=c.w;
            } else {
#pragma unroll
                for (int k = 0; k < 12; ++k) {
                    const int idx = g + k;
                    w[k] = (idx >= 0 && idx < N0) ? xr[idx] : 0.0f;
                }
            }
            float A0, D0, A1, D1;
            TAPSW(w + 2, A0, D0);                       // x[2i-6 .. 2i+1]
            TAPSW(w + 4, A1, D1);                       // x[2i-4 .. 2i+3]
            if (i + 1 < lhi) *reinterpret_cast<float2*>(dA + i) = make_float2(A0, A1);
            else             dA[i] = A0;
            if (i >= al) {                              // al even, i even
                if (i     < bl) outD[i]     = D0;       // M1 odd: scalar STG
                if (i + 1 < bl) outD[i + 1] = D1;
            }
        }
        __syncthreads();
    }

    // ---- Levels 2..6: pairs via smem (3 dense LDS.128 / pair) ----
    float* src  = bufA;
    float* dst  = bufB;
    int    ofsp = 8 + (lo[1] & 3);
#pragma unroll
    for (int l = 2; l <= 6; ++l) {
        const int llo  = lo[l], lhi = hi[l];
        const int wl   = lhi - llo;
        const int ofsc = 8 + (llo & 3);
        const int al   = tile * (TW << (6 - l));        // even
        const int bl   = min(al + (TW << (6 - l)), M[l]);

        if (l < 6 && tid < 16) dst[tid < 8 ? ofsc - 8 + tid : wl + ofsc - 8 + tid] = 0.0f;

        // window for pair (i,i+1): src floats 2i-8 .. 2i+3 ; base divisible by 4
        const int base = 2 * llo - 8 - lo[l - 1] + ofsp;
        const float4* sp = reinterpret_cast<const float4*>(src) + (base >> 2) + tid;
        float* outD = out + DOFF[l] + (size_t)row * M[l];
        float* dA   = dst + ofsc - llo;
        float* outA = out + (size_t)row * M[6];

        for (int i = llo + 2 * tid; i < lhi; i += 2 * THREADS, sp += THREADS) {
            const float4 a = sp[0], b = sp[1], c = sp[2];
            const float w[12] = {a.x, a.y, a.z, a.w, b.x, b.y, b.z, b.w,
                                 c.x, c.y, c.z, c.w};
            float A0, D0, A1, D1;
            TAPSW(w + 2, A0, D0);
            TAPSW(w + 4, A1, D1);
            if (l < 6) {
                if (i + 1 < lhi) *reinterpret_cast<float2*>(dA + i) = make_float2(A0, A1);
                else             dA[i] = A0;
                if (i >= al) {
                    if (l == 2) {                       // M2 odd: scalar STG
                        if (i     < bl) outD[i]     = D0;
                        if (i + 1 < bl) outD[i + 1] = D1;
                    } else {                            // M even: paired STG.64
                        if      (i + 1 < bl) *reinterpret_cast<float2*>(outD + i) = make_float2(D0, D1);
                        else if (i     < bl) outD[i] = D0;
                    }
                }
            } else {                                    // l==6: fully owned, even widths
                *reinterpret_cast<float2*>(outA + i) = make_float2(A0, A1);
                *reinterpret_cast<float2*>(outD + i) = make_float2(D0, D1);
            }
        }
        __syncthreads();
        float* t = src; src = dst; dst = t;
        ofsp = ofsc;
    }
}

extern "C" void kernel_launch(void* const* d_in, const int* in_sizes, int n_in,
                              void* d_out, int out_size)
{
    (void)in_sizes; (void)n_in; (void)out_size;
    dim3 grid(NTILES, 64);
    dwt6_kernel<<<grid, THREADS>>>((const float*)d_in[0], (float*)d_out);
}

// round 12
// speedup vs baseline: 1.0531x; 1.0531x over previous
#include <cuda_runtime.h>

#define THREADS 512
#define TW      240   // level-6 outputs per tile
#define NTILES  18    // ceil(4102 / 240)

// db4 reversed decomposition filters as literal immediates (FFMA-imm, rt=1)
#define RL0 ( 0.23037781330885523f)
#define RL1 ( 0.7148465705525415f)
#define RL2 ( 0.6308807679295904f)
#define RL3 (-0.02798376941698385f)
#define RL4 (-0.18703481171888114f)
#define RL5 ( 0.030841381835986965f)
#define RL6 ( 0.032883011666982945f)
#define RL7 (-0.010597401784997278f)
#define RH0 (-0.010597401784997278f)
#define RH1 (-0.032883011666982945f)
#define RH2 ( 0.030841381835986965f)
#define RH3 ( 0.18703481171888114f)
#define RH4 (-0.02798376941698385f)
#define RH5 (-0.6308807679295904f)
#define RH6 ( 0.7148465705525415f)
#define RH7 (-0.23037781330885523f)

// 8-tap A/D dot product on scalar window w[0..7]
#define TAPSW(w, A, D) do {                                             \
    A = (w)[0] * RL0;          D = (w)[0] * RH0;                        \
    A = fmaf((w)[1], RL1, A);  D = fmaf((w)[1], RH1, D);                \
    A = fmaf((w)[2], RL2, A);  D = fmaf((w)[2], RH2, D);                \
    A = fmaf((w)[3], RL3, A);  D = fmaf((w)[3], RH3, D);                \
    A = fmaf((w)[4], RL4, A);  D = fmaf((w)[4], RH4, D);                \
    A = fmaf((w)[5], RL5, A);  D = fmaf((w)[5], RH5, D);                \
    A = fmaf((w)[6], RL6, A);  D = fmaf((w)[6], RH6, D);                \
    A = fmaf((w)[7], RL7, A);  D = fmaf((w)[7], RH7, D);                \
} while (0)

__global__ __launch_bounds__(THREADS)
void dwt6_kernel(const float* __restrict__ x, float* __restrict__ out)
{
    // M[l] = length of cA_l per row (l=0 is the input)
    constexpr int M[7] = {262144, 131075, 65541, 32774, 16390, 8198, 4102};
    // Output element offsets: order cA6, cD6, cD5, cD4, cD3, cD2, cD1
    constexpr long long DOFF[7] = {0, 8390848LL, 4196224LL, 2098688LL,
                                   1049728LL, 525056LL, 262528LL};
    constexpr int N0 = 262144;

    // TW=240: w1 <= 7866 (+ofs<=10 +8), w2 <= 3930 (+18). 47.4 KB total.
    __shared__ __align__(16) float bufA[7888];
    __shared__ __align__(16) float bufB[3952];

    const int tile = blockIdx.x;   // 0..17
    const int row  = blockIdx.y;   // 0..63
    const int tid  = threadIdx.x;

    int lo[7], hi[7];
    lo[6] = tile * TW;
    hi[6] = min(lo[6] + TW, M[6]);
#pragma unroll
    for (int l = 5; l >= 1; --l) {
        lo[l] = max(2 * lo[l + 1] - 6, 0);   // always even
        hi[l] = min(2 * hi[l + 1], M[l]);
    }

    const float* xr = x + (size_t)row * N0;

    // ---- Level 1: pairs straight from gmem (3 dense LDG.128 / pair) ----
    {
        const int llo = lo[1], lhi = hi[1];
        const int ofs = 8 + (llo & 3);                  // data offset in bufA
        const int w1  = lhi - llo;
        const int al  = tile * (TW << 5);
        const int bl  = min(al + (TW << 5), M[1]);
        float* dA   = bufA + ofs - llo;
        float* outD = out + DOFF[1] + (size_t)row * M[1];

        if (tid < 16) bufA[tid < 8 ? ofs - 8 + tid : w1 + ofs - 8 + tid] = 0.0f;

        const bool interior = (2 * llo - 8 >= 0) && (2 * lhi + 2 <= N0);
        if (interior) {
            // pair (i,i+1) window = x[2i-8 .. 2i+3]; i step 2 -> 1 float4 step
            const float4* p = reinterpret_cast<const float4*>(xr + 2 * llo - 8) + tid;
            for (int i = llo + 2 * tid; i < lhi; i += 2 * THREADS, p += THREADS) {
                const float4 a = p[0], b = p[1], c = p[2];
                const float w[12] = {a.x, a.y, a.z, a.w, b.x, b.y, b.z, b.w,
                                     c.x, c.y, c.z, c.w};
                float A0, D0, A1, D1;
                TAPSW(w + 2, A0, D0);
                TAPSW(w + 4, A1, D1);
                *reinterpret_cast<float2*>(dA + i) = make_float2(A0, A1);  // width even
                if (i >= al) {                          // i < bl always (interior)
                    outD[i]     = D0;                   // M1 odd: scalar STG
                    outD[i + 1] = D1;
                }
            }
        } else {
            for (int i = llo + 2 * tid; i < lhi; i += 2 * THREADS) {
                const int g = 2 * i - 8;                // 16B-aligned
                float w[12];
                if (g >= 0 && g + 12 <= N0) {
                    const float4* p = reinterpret_cast<const float4*>(xr + g);
                    const float4 a = p[0], b = p[1], c = p[2];
                    w[0]=a.x; w[1]=a.y; w[2]=a.z;  w[3]=a.w;
                    w[4]=b.x; w[5]=b.y; w[6]=b.z;  w[7]=b.w;
                    w[8]=c.x; w[9]=c.y; w[10]=c.z; w[11]=c.w;
                } else {
#pragma unroll
                    for (int k = 0; k < 12; ++k) {
                        const int idx = g + k;
                        w[k] = (idx >= 0 && idx < N0) ? xr[idx] : 0.0f;
                    }
                }
                float A0, D0, A1, D1;
                TAPSW(w + 2, A0, D0);
                TAPSW(w + 4, A1, D1);
                if (i + 1 < lhi) *reinterpret_cast<float2*>(dA + i) = make_float2(A0, A1);
                else             dA[i] = A0;
                if (i >= al) {
                    if (i     < bl) outD[i]     = D0;
                    if (i + 1 < bl) outD[i + 1] = D1;
                }
            }
        }
        __syncthreads();
    }

    // ---- Levels 2..6: pairs via smem (3 dense LDS.128 / pair) ----
    float* src  = bufA;
    float* dst  = bufB;
    int    ofsp = 8 + (lo[1] & 3);
#pragma unroll
    for (int l = 2; l <= 6; ++l) {
        const int llo  = lo[l], lhi = hi[l];
        const int wl   = lhi - llo;
        const int ofsc = 8 + (llo & 3);
        const int al   = tile * (TW << (6 - l));        // even
        const int bl   = min(al + (TW << (6 - l)), M[l]);

        if (l < 6 && tid < 16) dst[tid < 8 ? ofsc - 8 + tid : wl + ofsc - 8 + tid] = 0.0f;

        // pair (i,i+1) window = src floats 2i-8 .. 2i+3 ; base divisible by 4
        const int base = 2 * llo - 8 - lo[l - 1] + ofsp;
        const float4* sp = reinterpret_cast<const float4*>(src) + (base >> 2) + tid;
        float* outD = out + DOFF[l] + (size_t)row * M[l];
        float* dA   = dst + ofsc - llo;
        float* outA = out + (size_t)row * M[6];

        for (int i = llo + 2 * tid; i < lhi; i += 2 * THREADS, sp += THREADS) {
            const float4 a = sp[0], b = sp[1], c = sp[2];
            const float w[12] = {a.x, a.y, a.z, a.w, b.x, b.y, b.z, b.w,
                                 c.x, c.y, c.z, c.w};
            float A0, D0, A1, D1;
            TAPSW(w + 2, A0, D0);
            TAPSW(w + 4, A1, D1);
            if (l < 6) {
                if (i + 1 < lhi) *reinterpret_cast<float2*>(dA + i) = make_float2(A0, A1);
                else             dA[i] = A0;
                if (i >= al) {
                    if (l == 2) {                       // M2 odd: scalar STG
                        if (i     < bl) outD[i]     = D0;
                        if (i + 1 < bl) outD[i + 1] = D1;
                    } else {                            // M even: paired STG.64
                        if      (i + 1 < bl) *reinterpret_cast<float2*>(outD + i) = make_float2(D0, D1);
                        else if (i     < bl) outD[i] = D0;
                    }
                }
            } else {                                    // l==6: fully owned, even widths
                *reinterpret_cast<float2*>(outA + i) = make_float2(A0, A1);
                *reinterpret_cast<float2*>(outD + i) = make_float2(D0, D1);
            }
        }
        __syncthreads();
        float* t = src; src = dst; dst = t;
        ofsp = ofsc;
    }
}

extern "C" void kernel_launch(void* const* d_in, const int* in_sizes, int n_in,
                              void* d_out, int out_size)
{
    (void)in_sizes; (void)n_in; (void)out_size;
    dim3 grid(NTILES, 64);
    dwt6_kernel<<<grid, THREADS>>>((const float*)d_in[0], (float*)d_out);
}

// round 13
// speedup vs baseline: 1.1973x; 1.1370x over previous
#include <cuda_runtime.h>

#define THREADS 480
#define TW      240   // level-6 outputs per tile
#define NTILES  18    // ceil(4102 / 240)

// db4 reversed decomposition filters as literal immediates (FFMA-imm, rt=1)
#define RL0 ( 0.23037781330885523f)
#define RL1 ( 0.7148465705525415f)
#define RL2 ( 0.6308807679295904f)
#define RL3 (-0.02798376941698385f)
#define RL4 (-0.18703481171888114f)
#define RL5 ( 0.030841381835986965f)
#define RL6 ( 0.032883011666982945f)
#define RL7 (-0.010597401784997278f)
#define RH0 (-0.010597401784997278f)
#define RH1 (-0.032883011666982945f)
#define RH2 ( 0.030841381835986965f)
#define RH3 ( 0.18703481171888114f)
#define RH4 (-0.02798376941698385f)
#define RH5 (-0.6308807679295904f)
#define RH6 ( 0.7148465705525415f)
#define RH7 (-0.23037781330885523f)

// 8-tap A/D dot product on scalar window w[0..7]
#define TAPSW(w, A, D) do {                                             \
    A = (w)[0] * RL0;          D = (w)[0] * RH0;                        \
    A = fmaf((w)[1], RL1, A);  D = fmaf((w)[1], RH1, D);                \
    A = fmaf((w)[2], RL2, A);  D = fmaf((w)[2], RH2, D);                \
    A = fmaf((w)[3], RL3, A);  D = fmaf((w)[3], RH3, D);                \
    A = fmaf((w)[4], RL4, A);  D = fmaf((w)[4], RH4, D);                \
    A = fmaf((w)[5], RL5, A);  D = fmaf((w)[5], RH5, D);                \
    A = fmaf((w)[6], RL6, A);  D = fmaf((w)[6], RH6, D);                \
    A = fmaf((w)[7], RL7, A);  D = fmaf((w)[7], RH7, D);                \
} while (0)

// A-only version (halo pairs: detail not stored)
#define TAPSWA(w, A) do {                                               \
    A = (w)[0] * RL0;                                                   \
    A = fmaf((w)[1], RL1, A);  A = fmaf((w)[2], RL2, A);                \
    A = fmaf((w)[3], RL3, A);  A = fmaf((w)[4], RL4, A);                \
    A = fmaf((w)[5], RL5, A);  A = fmaf((w)[6], RL6, A);                \
    A = fmaf((w)[7], RL7, A);                                           \
} while (0)

__device__ __forceinline__ void taps_pair(const float4 a, const float4 b, const float4 c,
                                          float& A0, float& D0, float& A1, float& D1)
{
    const float w[12] = {a.x, a.y, a.z, a.w, b.x, b.y, b.z, b.w, c.x, c.y, c.z, c.w};
    TAPSW(w + 2, A0, D0);
    TAPSW(w + 4, A1, D1);
}

__device__ __forceinline__ void taps_pairA(const float4 a, const float4 b, const float4 c,
                                           float& A0, float& A1)
{
    const float w[12] = {a.x, a.y, a.z, a.w, b.x, b.y, b.z, b.w, c.x, c.y, c.z, c.w};
    TAPSWA(w + 2, A0);
    TAPSWA(w + 4, A1);
}

// Interior level L (2..6): src/dst smem buffers with data offset 10,
// range [al-H, al+W), all constants compile-time. No clamping possible.
template<int L>
__device__ __forceinline__ void level_interior(const float* __restrict__ srcbuf,
        float* __restrict__ dstbuf, float* __restrict__ outD,
        float* __restrict__ outA, int al, int tid)
{
    constexpr int W     = TW << (6 - L);
    constexpr int H     = 6 * ((1 << (6 - L)) - 1);
    constexpr int HP    = H / 2;
    constexpr int WP    = W / 2;
    constexpr int ITERS = WP / THREADS;
    constexpr int REM   = WP % THREADS;

    const float4* s4 = reinterpret_cast<const float4*>(srcbuf);
    float2* d2 = reinterpret_cast<float2*>(dstbuf);

    if (tid < HP) {                      // halo pair k: i = al-H+2k, A only
        const float4 a = s4[tid + 2], b = s4[tid + 3], c = s4[tid + 4];
        float A0, A1;
        taps_pairA(a, b, c, A0, A1);
        d2[5 + tid] = make_float2(A0, A1);
    }
#pragma unroll 2
    for (int it = 0; it < ITERS; ++it) { // main pair m: i = al+2m, guard-free
        const int m = tid + it * THREADS;
        const float4 a = s4[m + HP + 2], b = s4[m + HP + 3], c = s4[m + HP + 4];
        float A0, D0, A1, D1;
        taps_pair(a, b, c, A0, D0, A1, D1);
        if (L < 6) d2[5 + HP + m] = make_float2(A0, A1);
        else *reinterpret_cast<float2*>(outA + al + 2 * m) = make_float2(A0, A1);
        if (L == 2) { outD[al + 2 * m] = D0; outD[al + 2 * m + 1] = D1; }  // M2 odd
        else *reinterpret_cast<float2*>(outD + al + 2 * m) = make_float2(D0, D1);
    }
    if (REM > 0 && tid < REM) {
        const int m = tid + ITERS * THREADS;
        const float4 a = s4[m + HP + 2], b = s4[m + HP + 3], c = s4[m + HP + 4];
        float A0, D0, A1, D1;
        taps_pair(a, b, c, A0, D0, A1, D1);
        if (L < 6) d2[5 + HP + m] = make_float2(A0, A1);
        else *reinterpret_cast<float2*>(outA + al + 2 * m) = make_float2(A0, A1);
        if (L == 2) { outD[al + 2 * m] = D0; outD[al + 2 * m + 1] = D1; }
        else *reinterpret_cast<float2*>(outD + al + 2 * m) = make_float2(D0, D1);
    }
}

// Interior level 1: source is gmem (all loads in-bounds for tiles 1..16)
__device__ __forceinline__ void level1_interior(const float* __restrict__ xr,
        float* __restrict__ bufA, float* __restrict__ outD, int al, int tid)
{
    constexpr int H = 186, HP = 93, WP = 3840, ITERS = WP / THREADS;  // 8
    float2* d2 = reinterpret_cast<float2*>(bufA);

    const float4* ph = reinterpret_cast<const float4*>(xr + 2 * (al - H) - 8);
    if (tid < HP) {
        const float4 a = ph[tid], b = ph[tid + 1], c = ph[tid + 2];
        float A0, A1;
        taps_pairA(a, b, c, A0, A1);
        d2[5 + tid] = make_float2(A0, A1);
    }
    const float4* pm = reinterpret_cast<const float4*>(xr + 2 * al - 8);
#pragma unroll 2
    for (int it = 0; it < ITERS; ++it) {
        const int m = tid + it * THREADS;
        const float4 a = pm[m], b = pm[m + 1], c = pm[m + 2];
        float A0, D0, A1, D1;
        taps_pair(a, b, c, A0, D0, A1, D1);
        d2[5 + HP + m] = make_float2(A0, A1);
        outD[al + 2 * m]     = D0;          // M1 odd: scalar STG
        outD[al + 2 * m + 1] = D1;
    }
}

__global__ __launch_bounds__(THREADS)
void dwt6_kernel(const float* __restrict__ x, float* __restrict__ out)
{
    constexpr int M[7] = {262144, 131075, 65541, 32774, 16390, 8198, 4102};
    constexpr long long DOFF[7] = {0, 8390848LL, 4196224LL, 2098688LL,
                                   1049728LL, 525056LL, 262528LL};
    constexpr int N0 = 262144;

    __shared__ __align__(16) float bufA[7888];
    __shared__ __align__(16) float bufB[3952];

    const int tile = blockIdx.x;   // 0..17
    const int row  = blockIdx.y;   // 0..63
    const int tid  = threadIdx.x;

    const float* xr = x + (size_t)row * N0;

    if (tile >= 1 && tile < NTILES - 1) {
        // ---------------- interior fast path: no clamping anywhere ----------
        float* outA = out + (size_t)row * M[6];
        level1_interior(xr, bufA, out + DOFF[1] + (size_t)row * M[1], tile * (TW << 5), tid);
        __syncthreads();
        level_interior<2>(bufA, bufB, out + DOFF[2] + (size_t)row * M[2], nullptr, tile * (TW << 4), tid);
        __syncthreads();
        level_interior<3>(bufB, bufA, out + DOFF[3] + (size_t)row * M[3], nullptr, tile * (TW << 3), tid);
        __syncthreads();
        level_interior<4>(bufA, bufB, out + DOFF[4] + (size_t)row * M[4], nullptr, tile * (TW << 2), tid);
        __syncthreads();
        level_interior<5>(bufB, bufA, out + DOFF[5] + (size_t)row * M[5], nullptr, tile * (TW << 1), tid);
        __syncthreads();
        level_interior<6>(bufA, nullptr, out + DOFF[6] + (size_t)row * M[6], outA, tile * TW, tid);
        return;
    }

    // ---------------- generic path (tiles 0 and 17): full clamping ---------
    int lo[7], hi[7];
    lo[6] = tile * TW;
    hi[6] = min(lo[6] + TW, M[6]);
#pragma unroll
    for (int l = 5; l >= 1; --l) {
        lo[l] = max(2 * lo[l + 1] - 6, 0);   // always even
        hi[l] = min(2 * hi[l + 1], M[l]);
    }

    // Level 1: pairs from gmem, bounds-checked
    {
        const int llo = lo[1], lhi = hi[1];
        const int ofs = 8 + (llo & 3);
        const int w1  = lhi - llo;
        const int al  = tile * (TW << 5);
        const int bl  = min(al + (TW << 5), M[1]);
        float* dA   = bufA + ofs - llo;
        float* outD = out + DOFF[1] + (size_t)row * M[1];

        if (tid < 16) bufA[tid < 8 ? ofs - 8 + tid : w1 + ofs - 8 + tid] = 0.0f;

        for (int i = llo + 2 * tid; i < lhi; i += 2 * THREADS) {
            const int g = 2 * i - 8;
            float w[12];
            if (g >= 0 && g + 12 <= N0) {
                const float4* p = reinterpret_cast<const float4*>(xr + g);
                const float4 a = p[0], b = p[1], c = p[2];
                w[0]=a.x; w[1]=a.y; w[2]=a.z;  w[3]=a.w;
                w[4]=b.x; w[5]=b.y; w[6]=b.z;  w[7]=b.w;
                w[8]=c.x; w[9]=c.y; w[10]=c.z; w[11]=c.w;
            } else {
#pragma unroll
                for (int k = 0; k < 12; ++k) {
                    const int idx = g + k;
                    w[k] = (idx >= 0 && idx < N0) ? xr[idx] : 0.0f;
                }
            }
            float A0, D0, A1, D1;
            TAPSW(w + 2, A0, D0);
            TAPSW(w + 4, A1, D1);
            if (i + 1 < lhi) *reinterpret_cast<float2*>(dA + i) = make_float2(A0, A1);
            else             dA[i] = A0;
            if (i >= al) {
                if (i     < bl) outD[i]     = D0;
                if (i + 1 < bl) outD[i + 1] = D1;
            }
        }
        __syncthreads();
    }

    // Levels 2..6 generic
    float* src  = bufA;
    float* dst  = bufB;
    int    ofsp = 8 + (lo[1] & 3);
#pragma unroll
    for (int l = 2; l <= 6; ++l) {
        const int llo  = lo[l], lhi = hi[l];
        const int wl   = lhi - llo;
        const int ofsc = 8 + (llo & 3);
        const int al   = tile * (TW << (6 - l));
        const int bl   = min(al + (TW << (6 - l)), M[l]);

        if (l < 6 && tid < 16) dst[tid < 8 ? ofsc - 8 + tid : wl + ofsc - 8 + tid] = 0.0f;

        const int base = 2 * llo - 8 - lo[l - 1] + ofsp;
        const float4* sp = reinterpret_cast<const float4*>(src) + (base >> 2) + tid;
        float* outD = out + DOFF[l] + (size_t)row * M[l];
        float* dA   = dst + ofsc - llo;
        float* outA = out + (size_t)row * M[6];

        for (int i = llo + 2 * tid; i < lhi; i += 2 * THREADS, sp += THREADS) {
            const float4 a = sp[0], b = sp[1], c = sp[2];
            float A0, D0, A1, D1;
            taps_pair(a, b, c, A0, D0, A1, D1);
            if (l < 6) {
                if (i + 1 < lhi) *reinterpret_cast<float2*>(dA + i) = make_float2(A0, A1);
                else             dA[i] = A0;
                if (i >= al) {
                    if (l == 2) {
                        if (i     < bl) outD[i]     = D0;
                        if (i + 1 < bl) outD[i + 1] = D1;
                    } else {
                        if      (i + 1 < bl) *reinterpret_cast<float2*>(outD + i) = make_float2(D0, D1);
                        else if (i     < bl) outD[i] = D0;
                    }
                }
            } else {
                if (i + 1 < bl) {
                    *reinterpret_cast<float2*>(outA + i) = make_float2(A0, A1);
                    *reinterpret_cast<float2*>(outD + i) = make_float2(D0, D1);
                } else if (i < bl) {
                    outA[i] = A0;
                    outD[i] = D0;
                }
            }
        }
        __syncthreads();
        float* t = src; src = dst; dst = t;
        ofsp = ofsc;
    }
}

extern "C" void kernel_launch(void* const* d_in, const int* in_sizes, int n_in,
                              void* d_out, int out_size)
{
    (void)in_sizes; (void)n_in; (void)out_size;
    dim3 grid(NTILES, 64);
    dwt6_kernel<<<grid, THREADS>>>((const float*)d_in[0], (float*)d_out);
}